// round 1
// baseline (speedup 1.0000x reference)
#include <cuda_runtime.h>
#include <math.h>

#define BATCH   16
#define NPB     36864      // boxes per batch = 64*64*9
#define THREADS 1024
#define PER_TH  36         // NPB / THREADS
#define TOPN    300
#define NGT     64
#define TPOS    64
#define NEGINF  (-1e30f)

// L2-resident scratch for decoded boxes (no cudaMalloc allowed)
__device__ float4 g_boxes[BATCH * NPB];

__global__ void __launch_bounds__(THREADS, 1)
roi_kernel(const float* __restrict__ deltas,
           const float* __restrict__ labels,
           const float* __restrict__ anchors,
           const float* __restrict__ gt,
           float* __restrict__ out)
{
    extern __shared__ float s_sc[];          // NPB scores
    __shared__ int    s_selidx[TOPN];
    __shared__ float4 s_nms[TOPN];
    __shared__ float  s_merged[TOPN];
    __shared__ int    s_gtbest[TOPN];
    __shared__ float4 s_gt4[NGT];
    __shared__ float  s_rs[32];
    __shared__ int    s_ri[32];
    __shared__ float4 s_selbox;
    __shared__ int    s_cursel;

    const int b = blockIdx.x;
    const int t = threadIdx.x;

    const float4* anc4 = (const float4*)(anchors) + (size_t)b * NPB;
    const float4* dlt4 = (const float4*)(deltas)  + (size_t)b * NPB;
    const float*  lab  = labels + (size_t)b * NPB;
    float4* boxes = g_boxes + (size_t)b * NPB;

    // ---- decode + load scores + initial per-thread argmax ----
    float lmax = -3.4e38f;
    int   lidx = 0x7fffffff;
    #pragma unroll 4
    for (int k = 0; k < PER_TH; ++k) {
        int i = t + k * THREADS;
        float4 a = anc4[i];
        float4 d = dlt4[i];
        float ah  = __fsub_rn(a.z, a.x);
        float aw  = __fsub_rn(a.w, a.y);
        float acy = __fadd_rn(a.x, __fmul_rn(0.5f, ah));
        float acx = __fadd_rn(a.y, __fmul_rn(0.5f, aw));
        float h   = __fmul_rn(expf(d.z), ah);
        float w   = __fmul_rn(expf(d.w), aw);
        float cy  = __fadd_rn(__fmul_rn(d.x, ah), acy);
        float cx  = __fadd_rn(__fmul_rn(d.y, aw), acx);
        float y1  = __fsub_rn(cy, __fmul_rn(0.5f, h));
        float x1  = __fsub_rn(cx, __fmul_rn(0.5f, w));
        boxes[i]  = make_float4(y1, x1, __fadd_rn(y1, h), __fadd_rn(x1, w));
        float s = lab[i];
        s_sc[i] = s;
        if (s > lmax) { lmax = s; lidx = i; }   // ascending i => first occurrence on ties
    }
    __syncthreads();

    // ---- sequential NMS: 300 iterations of (argmax, suppress+refresh-max) ----
    for (int it = 0; it < TOPN; ++it) {
        // block argmax with lowest-index tie-break
        float ms = lmax; int mi = lidx;
        #pragma unroll
        for (int o = 16; o > 0; o >>= 1) {
            float os = __shfl_down_sync(0xffffffffu, ms, o);
            int   oi = __shfl_down_sync(0xffffffffu, mi, o);
            if (os > ms || (os == ms && oi < mi)) { ms = os; mi = oi; }
        }
        if ((t & 31) == 0) { s_rs[t >> 5] = ms; s_ri[t >> 5] = mi; }
        __syncthreads();
        if (t < 32) {
            ms = s_rs[t]; mi = s_ri[t];
            #pragma unroll
            for (int o = 16; o > 0; o >>= 1) {
                float os = __shfl_down_sync(0xffffffffu, ms, o);
                int   oi = __shfl_down_sync(0xffffffffu, mi, o);
                if (os > ms || (os == ms && oi < mi)) { ms = os; mi = oi; }
            }
            if (t == 0) {
                if (ms > NEGINF * 0.5f) {       // valid = sc[idx] > NEG_INF/2
                    s_selidx[it] = mi;
                    s_cursel = mi;
                    s_selbox = boxes[mi];
                } else {
                    s_cursel = -1;
                    for (int j = it; j < TOPN; ++j) s_selidx[j] = -1;
                }
            }
        }
        __syncthreads();
        int sidx = s_cursel;
        if (sidx < 0) break;                    // uniform: nothing left alive
        float4 sb = s_selbox;
        float saa = __fmul_rn(__fsub_rn(sb.z, sb.x), __fsub_rn(sb.w, sb.y));

        // fused suppression + next-iteration per-thread argmax
        float nmax = -3.4e38f; int nidx = 0x7fffffff;
        #pragma unroll 4
        for (int k = 0; k < PER_TH; ++k) {
            int i = t + k * THREADS;
            float s = s_sc[i];
            if (s > NEGINF * 0.5f) {            // dead-skip: no box load for suppressed
                if (i == sidx) {
                    s_sc[i] = NEGINF;
                } else {
                    float4 bx = boxes[i];
                    float yy1 = fmaxf(sb.x, bx.x);
                    float xx1 = fmaxf(sb.y, bx.y);
                    float yy2 = fminf(sb.z, bx.z);
                    float xx2 = fminf(sb.w, bx.w);
                    float ih  = fmaxf(__fsub_rn(yy2, yy1), 0.f);
                    float iw  = fmaxf(__fsub_rn(xx2, xx1), 0.f);
                    float inter = __fmul_rn(ih, iw);
                    float ab = __fmul_rn(__fsub_rn(bx.z, bx.x), __fsub_rn(bx.w, bx.y));
                    float denom = __fadd_rn(__fsub_rn(__fadd_rn(saa, ab), inter), 1e-7f);
                    float iou = __fdiv_rn(inter, denom);
                    if (iou >= 0.5f) {
                        s_sc[i] = NEGINF;
                    } else if (s > nmax) {      // strict > keeps lowest index
                        nmax = s; nidx = i;
                    }
                }
            }
        }
        lmax = nmax; lidx = nidx;
        __syncthreads();
    }
    __syncthreads();

    // ---- build clipped nms_boxes (invalid -> zeros) ----
    for (int j = t; j < TOPN; j += THREADS) {
        int idx = s_selidx[j];
        float4 bx = make_float4(0.f, 0.f, 0.f, 0.f);
        if (idx >= 0) {
            float4 v = boxes[idx];
            bx.x = fminf(fmaxf(v.x, 0.f), 1.f);
            bx.y = fminf(fmaxf(v.y, 0.f), 1.f);
            bx.z = fminf(fmaxf(v.z, 0.f), 1.f);
            bx.w = fminf(fmaxf(v.w, 0.f), 1.f);
        }
        s_nms[j] = bx;
    }
    for (int j = t; j < NGT; j += THREADS) {
        s_gt4[j] = ((const float4*)gt)[(size_t)b * NGT + j];
    }
    __syncthreads();

    // ---- select_rois: merged = max IoU vs gt, gt_best = argmax (first occurrence) ----
    if (t < TOPN) {
        float4 a = s_nms[t];
        float aa = __fmul_rn(__fsub_rn(a.z, a.x), __fsub_rn(a.w, a.y));
        float mg = -1.f; int bi = 0;
        #pragma unroll 4
        for (int g = 0; g < NGT; ++g) {
            float4 gb = s_gt4[g];
            float yy1 = fmaxf(a.x, gb.x);
            float xx1 = fmaxf(a.y, gb.y);
            float yy2 = fminf(a.z, gb.z);
            float xx2 = fminf(a.w, gb.w);
            float inter = __fmul_rn(fmaxf(__fsub_rn(yy2, yy1), 0.f),
                                    fmaxf(__fsub_rn(xx2, xx1), 0.f));
            float ab = __fmul_rn(__fsub_rn(gb.z, gb.x), __fsub_rn(gb.w, gb.y));
            float denom = __fadd_rn(__fsub_rn(__fadd_rn(aa, ab), inter), 1e-7f);
            float iou = __fdiv_rn(inter, denom);
            if (iou > mg) { mg = iou; bi = g; }
        }
        s_merged[t] = mg; s_gtbest[t] = bi;
    }
    __syncthreads();

    // ---- stable descending rank (ties -> lower index first), emit top-64 ----
    if (t < TOPN) {
        float mg = s_merged[t];
        int r = 0;
        for (int j = 0; j < TOPN; ++j) {
            float mj = s_merged[j];
            if (mj > mg || (mj == mg && j < t)) ++r;
        }
        if (r < TPOS) {
            float4 a = s_nms[t];
            float* roi = out + ((size_t)b * 128 + r) * 4;
            roi[0] = a.x; roi[1] = a.y; roi[2] = a.z; roi[3] = a.w;
            out[(size_t)BATCH * 128 * 4 + (size_t)b * TPOS + r] = (float)s_gtbest[t];
        }
    }
    // neg rows 64..127 are zeros
    for (int j = t; j < 64 * 4; j += THREADS) {
        out[((size_t)b * 128 + TPOS) * 4 + j] = 0.f;
    }
}

extern "C" void kernel_launch(void* const* d_in, const int* in_sizes, int n_in,
                              void* d_out, int out_size) {
    const float* deltas  = (const float*)d_in[0];
    const float* labels  = (const float*)d_in[1];
    const float* anchors = (const float*)d_in[2];
    const float* gt      = (const float*)d_in[3];
    float* out = (float*)d_out;
    cudaFuncSetAttribute(roi_kernel, cudaFuncAttributeMaxDynamicSharedMemorySize,
                         NPB * (int)sizeof(float));
    roi_kernel<<<BATCH, THREADS, NPB * sizeof(float)>>>(deltas, labels, anchors, gt, out);
}

// round 2
// speedup vs baseline: 5.3522x; 5.3522x over previous
#include <cuda_runtime.h>
#include <math.h>

#define BATCH   16
#define NPB     36864      // boxes per batch = 64*64*9
#define THREADS 1024
#define PER_TH  36         // NPB / THREADS
#define TOPN    300
#define NGT     64
#define TPOS    64
#define CHUNK   1024
#define NEGINF  (-1e30f)

// L2-resident scratch (no cudaMalloc allowed)
__device__ float4   g_boxes[BATCH * NPB];
__device__ unsigned g_key[2][BATCH * NPB];
__device__ unsigned g_val[2][BATCH * NPB];

// dynamic smem layout (u32 units):
//  [0, 32768)         : intra-chunk suppression mask (1024 rows x 32 words)  [phase C]
//                       aliased by radix counters u32[16384]                 [phase B]
//  [32768, 36864)     : chunk boxes float4[1024]
//  [36864, 37888)     : chunk global-idx u32[1024]
#define DYN_U32  37888
#define DYN_BYTES (DYN_U32 * 4)

__global__ void __launch_bounds__(THREADS, 1)
roi_kernel(const float* __restrict__ deltas,
           const float* __restrict__ labels,
           const float* __restrict__ anchors,
           const float* __restrict__ gt,
           float* __restrict__ out)
{
    extern __shared__ unsigned s_dyn[];
    unsigned* s_mask = s_dyn;                          // phase C
    unsigned* s_cnt  = s_dyn;                          // phase B (alias)
    float4*   s_cbox = (float4*)(s_dyn + 32768);
    unsigned* s_cidx = s_dyn + 32768 + 4096;

    __shared__ float4   s_sel[TOPN];     // selected (unclipped) boxes
    __shared__ int      s_selg[TOPN];    // selected global box index
    __shared__ int      s_ncur;
    __shared__ unsigned s_alive[32];
    __shared__ unsigned s_warp[32];
    __shared__ float4   s_nms[TOPN];
    __shared__ float    s_merged[TOPN];
    __shared__ int      s_gtbest[TOPN];
    __shared__ float4   s_gt4[NGT];

    const int b = blockIdx.x;
    const int t = threadIdx.x;

    const float4* anc4 = (const float4*)(anchors) + (size_t)b * NPB;
    const float4* dlt4 = (const float4*)(deltas)  + (size_t)b * NPB;
    const float*  lab  = labels + (size_t)b * NPB;
    float4* boxes = g_boxes + (size_t)b * NPB;

    // ================= Phase A: decode + build sort keys =================
    unsigned* k0 = g_key[0] + (size_t)b * NPB;
    unsigned* v0 = g_val[0] + (size_t)b * NPB;
    #pragma unroll 4
    for (int k = 0; k < PER_TH; ++k) {
        int i = t + k * THREADS;
        float4 a = anc4[i];
        float4 d = dlt4[i];
        float ah  = __fsub_rn(a.z, a.x);
        float aw  = __fsub_rn(a.w, a.y);
        float acy = __fadd_rn(a.x, __fmul_rn(0.5f, ah));
        float acx = __fadd_rn(a.y, __fmul_rn(0.5f, aw));
        float h   = __fmul_rn(expf(d.z), ah);
        float w   = __fmul_rn(expf(d.w), aw);
        float cy  = __fadd_rn(__fmul_rn(d.x, ah), acy);
        float cx  = __fadd_rn(__fmul_rn(d.y, aw), acx);
        float y1  = __fsub_rn(cy, __fmul_rn(0.5f, h));
        float x1  = __fsub_rn(cx, __fmul_rn(0.5f, w));
        boxes[i]  = make_float4(y1, x1, __fadd_rn(y1, h), __fadd_rn(x1, w));
        // scores are uniform[0,1): non-negative => bit pattern is order-isomorphic.
        // key = ~bits  => ascending sort == descending score; stable sort keeps
        // equal scores in ascending index order (== argmax first-occurrence).
        k0[i] = ~__float_as_uint(lab[i]);
        v0[i] = (unsigned)i;
    }
    __syncthreads();

    // ================= Phase B: stable LSD radix sort (8 x 4 bits) ========
    for (int pass = 0; pass < 8; ++pass) {
        const int shift = pass * 4;
        const unsigned* kin  = g_key[pass & 1]       + (size_t)b * NPB;
        const unsigned* vin  = g_val[pass & 1]       + (size_t)b * NPB;
        unsigned*       kout = g_key[(pass & 1) ^ 1] + (size_t)b * NPB;
        unsigned*       vout = g_val[(pass & 1) ^ 1] + (size_t)b * NPB;

        #pragma unroll
        for (int c = 0; c < 16; ++c) s_cnt[c * 1024 + t] = 0;
        __syncthreads();

        const int base = t * PER_TH;          // blocked ownership => stability
        unsigned dig[5] = {0, 0, 0, 0, 0};    // 36 packed 4-bit digits
        #pragma unroll
        for (int k = 0; k < PER_TH; ++k) {
            unsigned d = (kin[base + k] >> shift) & 15u;
            dig[k >> 3] |= d << ((k & 7) * 4);
            s_cnt[d * 1024 + t] += 1u;        // bank = t%32 -> conflict-free
        }
        __syncthreads();

        // exclusive scan of the 16384 counters in flat (digit-major) order
        unsigned v[16], sum = 0;
        #pragma unroll
        for (int j = 0; j < 16; ++j) v[j] = s_cnt[t * 16 + j];
        #pragma unroll
        for (int j = 0; j < 16; ++j) { unsigned tmp = v[j]; v[j] = sum; sum += tmp; }
        unsigned lane = t & 31, wid = t >> 5;
        unsigned x = sum;
        #pragma unroll
        for (int o = 1; o < 32; o <<= 1) {
            unsigned y = __shfl_up_sync(0xffffffffu, x, o);
            if (lane >= o) x += y;
        }
        if (lane == 31) s_warp[wid] = x;
        __syncthreads();
        if (t < 32) {
            unsigned wsum = s_warp[t];
            unsigned xx = wsum;
            #pragma unroll
            for (int o = 1; o < 32; o <<= 1) {
                unsigned y = __shfl_up_sync(0xffffffffu, xx, o);
                if (t >= o) xx += y;
            }
            s_warp[t] = xx - wsum;            // exclusive warp offset
        }
        __syncthreads();
        unsigned prefix = s_warp[wid] + (x - sum);
        #pragma unroll
        for (int j = 0; j < 16; ++j) s_cnt[t * 16 + j] = v[j] + prefix;
        __syncthreads();

        // stable scatter
        #pragma unroll
        for (int k = 0; k < PER_TH; ++k) {
            unsigned d = (dig[k >> 3] >> ((k & 7) * 4)) & 15u;
            unsigned p = s_cnt[d * 1024 + t]++;
            kout[p] = kin[base + k];
            vout[p] = vin[base + k];
        }
        __syncthreads();
    }
    // sorted order now in g_val[0]

    // ================= Phase C: chunked greedy NMS ========================
    const unsigned* sidx = g_val[0] + (size_t)b * NPB;
    if (t == 0) s_ncur = 0;
    __syncthreads();

    for (int pos = 0; pos < NPB; pos += CHUNK) {
        int ncur = s_ncur;
        if (ncur >= TOPN) break;

        // load chunk candidates (gather via sorted index)
        int gi = pos + t;
        bool ok = gi < NPB;
        unsigned ci = 0;
        float4 bx = make_float4(0.f, 0.f, 0.f, 0.f);
        if (ok) { ci = sidx[gi]; bx = boxes[ci]; }
        s_cbox[t] = bx;
        s_cidx[t] = ci;

        // kill candidates overlapping any already-selected box
        bool alive = ok;
        for (int j = 0; j < ncur && alive; ++j) {
            float4 sb = s_sel[j];
            float saa = __fmul_rn(__fsub_rn(sb.z, sb.x), __fsub_rn(sb.w, sb.y));
            float yy1 = fmaxf(sb.x, bx.x);
            float xx1 = fmaxf(sb.y, bx.y);
            float yy2 = fminf(sb.z, bx.z);
            float xx2 = fminf(sb.w, bx.w);
            float inter = __fmul_rn(fmaxf(__fsub_rn(yy2, yy1), 0.f),
                                    fmaxf(__fsub_rn(xx2, xx1), 0.f));
            float ab = __fmul_rn(__fsub_rn(bx.z, bx.x), __fsub_rn(bx.w, bx.y));
            float denom = __fadd_rn(__fsub_rn(__fadd_rn(saa, ab), inter), 1e-7f);
            if (__fdiv_rn(inter, denom) >= 0.5f) alive = false;
        }
        unsigned am = __ballot_sync(0xffffffffu, alive);
        if ((t & 31) == 0) s_alive[t >> 5] = am;

        // zero intra-chunk suppression mask
        #pragma unroll
        for (int w = 0; w < 32; ++w) s_mask[w * 1024 + t] = 0;
        __syncthreads();

        // balanced pair enumeration: each unordered pair exactly once
        for (int d = 1; d <= 512; ++d) {
            if (d == 512 && t >= 512) break;
            int o = t + d; if (o >= 1024) o -= 1024;
            int a = t < o ? t : o;           // earlier candidate = suppressor
            int c = t < o ? o : t;
            float4 A = s_cbox[a];
            float4 C = s_cbox[c];
            float aa = __fmul_rn(__fsub_rn(A.z, A.x), __fsub_rn(A.w, A.y));
            float yy1 = fmaxf(A.x, C.x);
            float xx1 = fmaxf(A.y, C.y);
            float yy2 = fminf(A.z, C.z);
            float xx2 = fminf(A.w, C.w);
            float inter = __fmul_rn(fmaxf(__fsub_rn(yy2, yy1), 0.f),
                                    fmaxf(__fsub_rn(xx2, xx1), 0.f));
            float cc = __fmul_rn(__fsub_rn(C.z, C.x), __fsub_rn(C.w, C.y));
            float denom = __fadd_rn(__fsub_rn(__fadd_rn(aa, cc), inter), 1e-7f);
            if (__fdiv_rn(inter, denom) >= 0.5f)
                atomicOr(&s_mask[a * 32 + (c >> 5)], 1u << (c & 31));
        }
        __syncthreads();

        // sequential resolution by warp 0 over the bitmask
        if (t < 32) {
            unsigned dead = 0;                 // lane l owns dead word l
            unsigned aliveW = s_alive[t];
            int n = ncur;
            for (int w = 0; w < 32 && n < TOPN; ++w) {
                unsigned cur = __shfl_sync(0xffffffffu, aliveW & ~dead, w);
                while (cur && n < TOPN) {
                    int bitp = __ffs(cur) - 1;
                    int i = w * 32 + bitp;
                    cur &= cur - 1;
                    if (t == 0) { s_sel[n] = s_cbox[i]; s_selg[n] = (int)s_cidx[i]; }
                    n++;
                    unsigned row = s_mask[i * 32 + t];
                    dead |= row;
                    unsigned rw = __shfl_sync(0xffffffffu, row, w);
                    cur &= ~rw;
                }
            }
            if (t == 0) s_ncur = n;
        }
        __syncthreads();
    }
    __syncthreads();
    const int nsel = s_ncur;

    // ================= Phase D: clip, select_rois, rank, emit =============
    for (int j = t; j < TOPN; j += THREADS) {
        float4 bx = make_float4(0.f, 0.f, 0.f, 0.f);
        if (j < nsel) {
            float4 vv = s_sel[j];
            bx.x = fminf(fmaxf(vv.x, 0.f), 1.f);
            bx.y = fminf(fmaxf(vv.y, 0.f), 1.f);
            bx.z = fminf(fmaxf(vv.z, 0.f), 1.f);
            bx.w = fminf(fmaxf(vv.w, 0.f), 1.f);
        }
        s_nms[j] = bx;
    }
    for (int j = t; j < NGT; j += THREADS) {
        s_gt4[j] = ((const float4*)gt)[(size_t)b * NGT + j];
    }
    __syncthreads();

    if (t < TOPN) {
        float4 a = s_nms[t];
        float aa = __fmul_rn(__fsub_rn(a.z, a.x), __fsub_rn(a.w, a.y));
        float mg = -1.f; int bi = 0;
        #pragma unroll 4
        for (int g = 0; g < NGT; ++g) {
            float4 gb = s_gt4[g];
            float yy1 = fmaxf(a.x, gb.x);
            float xx1 = fmaxf(a.y, gb.y);
            float yy2 = fminf(a.z, gb.z);
            float xx2 = fminf(a.w, gb.w);
            float inter = __fmul_rn(fmaxf(__fsub_rn(yy2, yy1), 0.f),
                                    fmaxf(__fsub_rn(xx2, xx1), 0.f));
            float ab = __fmul_rn(__fsub_rn(gb.z, gb.x), __fsub_rn(gb.w, gb.y));
            float denom = __fadd_rn(__fsub_rn(__fadd_rn(aa, ab), inter), 1e-7f);
            float iou = __fdiv_rn(inter, denom);
            if (iou > mg) { mg = iou; bi = g; }
        }
        s_merged[t] = mg; s_gtbest[t] = bi;
    }
    __syncthreads();

    if (t < TOPN) {
        float mg = s_merged[t];
        int r = 0;
        for (int j = 0; j < TOPN; ++j) {
            float mj = s_merged[j];
            if (mj > mg || (mj == mg && j < t)) ++r;
        }
        if (r < TPOS) {
            float4 a = s_nms[t];
            float* roi = out + ((size_t)b * 128 + r) * 4;
            roi[0] = a.x; roi[1] = a.y; roi[2] = a.z; roi[3] = a.w;
            out[(size_t)BATCH * 128 * 4 + (size_t)b * TPOS + r] = (float)s_gtbest[t];
        }
    }
    // neg rows 64..127 are zeros
    for (int j = t; j < 64 * 4; j += THREADS) {
        out[((size_t)b * 128 + TPOS) * 4 + j] = 0.f;
    }
}

extern "C" void kernel_launch(void* const* d_in, const int* in_sizes, int n_in,
                              void* d_out, int out_size) {
    const float* deltas  = (const float*)d_in[0];
    const float* labels  = (const float*)d_in[1];
    const float* anchors = (const float*)d_in[2];
    const float* gt      = (const float*)d_in[3];
    float* out = (float*)d_out;
    cudaFuncSetAttribute(roi_kernel, cudaFuncAttributeMaxDynamicSharedMemorySize,
                         DYN_BYTES);
    roi_kernel<<<BATCH, THREADS, DYN_BYTES>>>(deltas, labels, anchors, gt, out);
}

// round 4
// speedup vs baseline: 20.6764x; 3.8632x over previous
#include <cuda_runtime.h>
#include <math.h>

#define BATCH   16
#define NPB     36864      // boxes per batch = 64*64*9
#define THREADS 1024
#define PER_TH  36         // NPB / THREADS
#define TOPN    300
#define NGT     64
#define TPOS    64
#define NBUCK   4096
#define SLABSZ  7936u
#define NSLAB   5          // ceil(36864/7936)
#define PPOW    8192       // bitonic size

// L2-resident scratch (no cudaMalloc allowed)
__device__ float4   g_boxes[BATCH * NPB];
__device__ unsigned g_k30[BATCH * NPB];

// dynamic smem layout (u32 units):
//  [0, 16384)       s_key u64[8192]   (aliased by s_hist u32[4096] during phase A)
//  [16384, 20481)   s_cum u32[4097]
//  [20484, 24580)   s_kbox float4[1024]
#define OFF_CUM   16384
#define OFF_KBOX  20484
#define DYN_U32   24580
#define DYN_BYTES (DYN_U32 * 4)

// bucket from descending key30 (monotone-consistent with key order):
// score = bits(0x3F7FFFFF - key30); bucket 0 = highest scores.
__device__ __forceinline__ unsigned bucket_of(unsigned key30) {
    float s = __uint_as_float(0x3F7FFFFFu - key30);
    unsigned q = (unsigned)__fmul_rn(s, 4096.f);
    if (q > 4095u) q = 4095u;
    return 4095u - q;
}

// Exact-threshold suppression test: matches rn(inter/denom) >= 0.5 with a
// guard band; falls back to the exact division only near the boundary.
__device__ __forceinline__ bool suppress_test(float4 sb, float sa, float4 bx, float ab) {
    float yy1 = fmaxf(sb.x, bx.x);
    float xx1 = fmaxf(sb.y, bx.y);
    float yy2 = fminf(sb.z, bx.z);
    float xx2 = fminf(sb.w, bx.w);
    float ih  = fmaxf(__fsub_rn(yy2, yy1), 0.f);
    float iw  = fmaxf(__fsub_rn(xx2, xx1), 0.f);
    float inter = __fmul_rn(ih, iw);
    float denom = __fadd_rn(__fsub_rn(__fadd_rn(sa, ab), inter), 1e-7f);
    float e = __fmaf_rn(-0.5f, denom, inter);     // inter - 0.5*denom
    float margin = __fmul_rn(denom, 1e-4f);
    if (e < -margin) return false;
    if (e >  margin) return true;
    return __fdiv_rn(inter, denom) >= 0.5f;       // exact reference semantics
}

__global__ void __launch_bounds__(THREADS, 1)
roi_kernel(const float* __restrict__ deltas,
           const float* __restrict__ labels,
           const float* __restrict__ anchors,
           const float* __restrict__ gt,
           float* __restrict__ out)
{
    extern __shared__ unsigned s_dyn[];
    unsigned long long* s_key = (unsigned long long*)s_dyn;
    unsigned* s_hist = s_dyn;                       // alias (phase A only)
    unsigned* s_cum  = s_dyn + OFF_CUM;             // 4097 entries
    float4*   s_kbox = (float4*)(s_dyn + OFF_KBOX); // 1024 compacted boxes

    __shared__ float4 s_sel[TOPN];
    __shared__ float  s_sela[TOPN];
    __shared__ float4 s_nms[TOPN];
    __shared__ float  s_merged[TOPN];
    __shared__ int    s_gtbest[TOPN];
    __shared__ float4 s_gt4[NGT];
    __shared__ unsigned s_warp[32];
    __shared__ unsigned s_kal[32];
    __shared__ int    s_ncur, s_m, s_m2, s_curslot;
    __shared__ float4 s_selbox;
    __shared__ float  s_selarea;

    const int b = blockIdx.x;
    const int t = threadIdx.x;
    const int lane = t & 31, wid = t >> 5;

    const float4* anc4 = (const float4*)(anchors) + (size_t)b * NPB;
    const float4* dlt4 = (const float4*)(deltas)  + (size_t)b * NPB;
    const float*  lab  = labels + (size_t)b * NPB;
    float4*   boxes = g_boxes + (size_t)b * NPB;
    unsigned* k30g  = g_k30  + (size_t)b * NPB;

    // ================= Phase A: decode + key30 + bucket histogram ==========
    #pragma unroll
    for (int c = 0; c < 4; ++c) s_hist[c * 1024 + t] = 0;
    if (t == 0) s_ncur = 0;
    __syncthreads();

    #pragma unroll 4
    for (int k = 0; k < PER_TH; ++k) {
        int i = t + k * THREADS;
        float4 a = anc4[i];
        float4 d = dlt4[i];
        float ah  = __fsub_rn(a.z, a.x);
        float aw  = __fsub_rn(a.w, a.y);
        float acy = __fadd_rn(a.x, __fmul_rn(0.5f, ah));
        float acx = __fadd_rn(a.y, __fmul_rn(0.5f, aw));
        float h   = __fmul_rn(expf(d.z), ah);
        float w   = __fmul_rn(expf(d.w), aw);
        float cy  = __fadd_rn(__fmul_rn(d.x, ah), acy);
        float cx  = __fadd_rn(__fmul_rn(d.y, aw), acx);
        float y1  = __fsub_rn(cy, __fmul_rn(0.5f, h));
        float x1  = __fsub_rn(cx, __fmul_rn(0.5f, w));
        boxes[i]  = make_float4(y1, x1, __fadd_rn(y1, h), __fadd_rn(x1, w));
        // uniform [0,1) scores: bits order-isomorphic; descending key, 30 bits
        unsigned key30 = 0x3F7FFFFFu - __float_as_uint(lab[i]);
        k30g[i] = key30;
        atomicAdd(&s_hist[bucket_of(key30)], 1u);
    }
    __syncthreads();

    // ================= Phase B: exclusive scan of 4096 bucket counts =======
    {
        unsigned v[4], sum = 0;
        #pragma unroll
        for (int j = 0; j < 4; ++j) { v[j] = s_hist[t * 4 + j]; }
        unsigned e[4];
        #pragma unroll
        for (int j = 0; j < 4; ++j) { e[j] = sum; sum += v[j]; }
        unsigned x = sum;
        #pragma unroll
        for (int o = 1; o < 32; o <<= 1) {
            unsigned y = __shfl_up_sync(0xffffffffu, x, o);
            if (lane >= o) x += y;
        }
        if (lane == 31) s_warp[wid] = x;
        __syncthreads();
        if (t < 32) {
            unsigned wsum = s_warp[t], xx = wsum;
            #pragma unroll
            for (int o = 1; o < 32; o <<= 1) {
                unsigned y = __shfl_up_sync(0xffffffffu, xx, o);
                if (t >= o) xx += y;
            }
            s_warp[t] = xx - wsum;
        }
        __syncthreads();
        unsigned prefix = s_warp[wid] + (x - sum);
        #pragma unroll
        for (int j = 0; j < 4; ++j) s_cum[t * 4 + j] = prefix + e[j];
        if (t == THREADS - 1) s_cum[NBUCK] = prefix + sum;
        __syncthreads();
    }

    // ================= Phase C: slabs (gather -> bitonic -> greedy NMS) ====
    for (int slab = 0; slab < NSLAB; ++slab) {
        if (s_ncur >= TOPN) break;            // uniform (post-sync)
        if (t == 0) s_m = 0;
        __syncthreads();

        // gather slab members (coalesced re-scan of key30)
        #pragma unroll 4
        for (int k = 0; k < PER_TH; ++k) {
            int i = t + k * THREADS;
            unsigned key30 = k30g[i];
            unsigned bk = bucket_of(key30);
            if (s_cum[bk] / SLABSZ == (unsigned)slab) {
                int pos = atomicAdd(&s_m, 1);
                if (pos < PPOW)
                    s_key[pos] = ((unsigned long long)key30 << 16) | (unsigned)i;
            }
        }
        __syncthreads();
        int m = s_m; if (m > PPOW) m = PPOW;
        for (int i = t; i < PPOW; i += THREADS)
            if (i >= m) s_key[i] = ~0ull;
        __syncthreads();

        // bitonic sort PPOW u64 keys ascending (score desc, idx asc)
        for (int k = 2; k <= PPOW; k <<= 1) {
            for (int j = k >> 1; j > 0; j >>= 1) {
                #pragma unroll 2
                for (int n = t; n < PPOW; n += THREADS) {
                    int ixj = n ^ j;
                    if (ixj > n) {
                        bool up = ((n & k) == 0);
                        unsigned long long va = s_key[n], vb = s_key[ixj];
                        if ((va > vb) == up) { s_key[n] = vb; s_key[ixj] = va; }
                    }
                }
                __syncthreads();
            }
        }

        // NMS over sorted slab in chunks of 1024
        for (int pos = 0; pos < m; pos += THREADS) {
            if (s_ncur >= TOPN) break;        // uniform (post-sync)
            int nc = s_ncur;

            int ci = pos + t;
            bool alive = ci < m;
            float4 bx = make_float4(0.f, 0.f, 0.f, 0.f);
            float  ab = 0.f;
            if (alive) {
                unsigned gidx = (unsigned)(s_key[ci] & 0xFFFFu);
                bx = boxes[gidx];
                ab = __fmul_rn(__fsub_rn(bx.z, bx.x), __fsub_rn(bx.w, bx.y));
            }

            // prekill vs already-selected (serial early-exit)
            for (int j = 0; j < nc && alive; ++j) {
                if (suppress_test(s_sel[j], s_sela[j], bx, ab)) alive = false;
            }

            // compact alive candidates (order-preserving)
            unsigned bal = __ballot_sync(0xffffffffu, alive);
            if (lane == 0) s_warp[wid] = __popc(bal);
            __syncthreads();
            if (t < 32) {
                unsigned wsum = s_warp[t], xx = wsum;
                #pragma unroll
                for (int o = 1; o < 32; o <<= 1) {
                    unsigned y = __shfl_up_sync(0xffffffffu, xx, o);
                    if (t >= o) xx += y;
                }
                s_warp[t] = xx - wsum;
                if (t == 31) s_m2 = (int)xx;
            }
            __syncthreads();
            if (alive) {
                int cpos = (int)s_warp[wid] + __popc(bal & ((1u << lane) - 1u));
                s_kbox[cpos] = bx;
            }
            __syncthreads();
            int M = s_m2;

            // re-own compacted slot t
            bool alive2 = t < M;
            float4 bx2 = make_float4(0.f, 0.f, 0.f, 0.f);
            float  ab2 = 0.f;
            if (alive2) {
                bx2 = s_kbox[t];
                ab2 = __fmul_rn(__fsub_rn(bx2.z, bx2.x), __fsub_rn(bx2.w, bx2.y));
            }
            {
                unsigned b2 = __ballot_sync(0xffffffffu, alive2);
                if (lane == 0) s_kal[wid] = b2;
            }
            __syncthreads();

            // serial greedy over compacted list
            while (true) {
                if (s_ncur >= TOPN) break;    // uniform
                if (t < 32) {
                    unsigned w = s_kal[t];
                    unsigned nb = __ballot_sync(0xffffffffu, w != 0u);
                    int f = nb ? (__ffs(nb) - 1) : 0;
                    unsigned wf = __shfl_sync(0xffffffffu, w, f);
                    if (t == 0) {
                        if (nb == 0u) s_curslot = -1;
                        else {
                            int slot = f * 32 + (__ffs(wf) - 1);
                            s_curslot = slot;
                            float4 sb = s_kbox[slot];
                            float sa = __fmul_rn(__fsub_rn(sb.z, sb.x),
                                                 __fsub_rn(sb.w, sb.y));
                            s_selbox = sb; s_selarea = sa;
                            int n = s_ncur;
                            s_sel[n] = sb; s_sela[n] = sa;
                            s_ncur = n + 1;
                        }
                    }
                }
                __syncthreads();
                int slot = s_curslot;
                if (slot < 0) break;          // uniform
                if (alive2) {
                    if (t == slot) alive2 = false;
                    else if (suppress_test(s_selbox, s_selarea, bx2, ab2)) alive2 = false;
                }
                unsigned b2 = __ballot_sync(0xffffffffu, alive2);
                if (lane == 0) s_kal[wid] = b2;
                __syncthreads();
            }
            __syncthreads();
        }
        __syncthreads();
    }
    __syncthreads();
    const int nsel = s_ncur;

    // ================= Phase D: clip, select_rois, rank, emit ==============
    for (int j = t; j < TOPN; j += THREADS) {
        float4 bxo = make_float4(0.f, 0.f, 0.f, 0.f);
        if (j < nsel) {
            float4 vv = s_sel[j];
            bxo.x = fminf(fmaxf(vv.x, 0.f), 1.f);
            bxo.y = fminf(fmaxf(vv.y, 0.f), 1.f);
            bxo.z = fminf(fmaxf(vv.z, 0.f), 1.f);
            bxo.w = fminf(fmaxf(vv.w, 0.f), 1.f);
        }
        s_nms[j] = bxo;
    }
    for (int j = t; j < NGT; j += THREADS) {
        s_gt4[j] = ((const float4*)gt)[(size_t)b * NGT + j];
    }
    __syncthreads();

    if (t < TOPN) {
        float4 a = s_nms[t];
        float aa = __fmul_rn(__fsub_rn(a.z, a.x), __fsub_rn(a.w, a.y));
        float mg = -1.f; int bi = 0;
        #pragma unroll 4
        for (int g = 0; g < NGT; ++g) {
            float4 gb = s_gt4[g];
            float yy1 = fmaxf(a.x, gb.x);
            float xx1 = fmaxf(a.y, gb.y);
            float yy2 = fminf(a.z, gb.z);
            float xx2 = fminf(a.w, gb.w);
            float inter = __fmul_rn(fmaxf(__fsub_rn(yy2, yy1), 0.f),
                                    fmaxf(__fsub_rn(xx2, xx1), 0.f));
            float gba = __fmul_rn(__fsub_rn(gb.z, gb.x), __fsub_rn(gb.w, gb.y));
            float denom = __fadd_rn(__fsub_rn(__fadd_rn(aa, gba), inter), 1e-7f);
            float iou = __fdiv_rn(inter, denom);
            if (iou > mg) { mg = iou; bi = g; }
        }
        s_merged[t] = mg; s_gtbest[t] = bi;
    }
    __syncthreads();

    if (t < TOPN) {
        float mg = s_merged[t];
        int r = 0;
        for (int j = 0; j < TOPN; ++j) {
            float mj = s_merged[j];
            if (mj > mg || (mj == mg && j < t)) ++r;
        }
        if (r < TPOS) {
            float4 a = s_nms[t];
            float* roi = out + ((size_t)b * 128 + r) * 4;
            roi[0] = a.x; roi[1] = a.y; roi[2] = a.z; roi[3] = a.w;
            out[(size_t)BATCH * 128 * 4 + (size_t)b * TPOS + r] = (float)s_gtbest[t];
        }
    }
    for (int j = t; j < 64 * 4; j += THREADS) {
        out[((size_t)b * 128 + TPOS) * 4 + j] = 0.f;
    }
}

extern "C" void kernel_launch(void* const* d_in, const int* in_sizes, int n_in,
                              void* d_out, int out_size) {
    const float* deltas  = (const float*)d_in[0];
    const float* labels  = (const float*)d_in[1];
    const float* anchors = (const float*)d_in[2];
    const float* gt      = (const float*)d_in[3];
    float* out = (float*)d_out;
    cudaFuncSetAttribute(roi_kernel, cudaFuncAttributeMaxDynamicSharedMemorySize,
                         DYN_BYTES);
    roi_kernel<<<BATCH, THREADS, DYN_BYTES>>>(deltas, labels, anchors, gt, out);
}

// round 5
// speedup vs baseline: 23.1674x; 1.1205x over previous
#include <cuda_runtime.h>
#include <math.h>

#define BATCH   16
#define NPB     36864      // boxes per batch = 64*64*9
#define THREADS 1024
#define PER_TH  36         // NPB / THREADS
#define TOPN    300
#define NGT     64
#define TPOS    64
#define NBUCK   4096
#define SLABSZ  7936u
#define NSLAB   5          // ceil(36864/7936)
#define PPOW    8192       // bitonic size
#define CHK     512        // NMS chunk size

// L2-resident scratch (no cudaMalloc allowed)
__device__ float4   g_boxes[BATCH * NPB];
__device__ unsigned g_k30[BATCH * NPB];

// dynamic smem layout (u32 units):
//  [0, 16384)        s_key u64[8192]   (aliased by s_hist u32[4096] in phase A)
//  [16384, 20481)    s_cum u32[4097]
//  [20484, 22532)    s_kbox float4[512]
//  [22532, 30724)    s_mask u32[512*16]
#define OFF_CUM   16384
#define OFF_KBOX  20484
#define OFF_MASK  22532
#define DYN_U32   30724
#define DYN_BYTES (DYN_U32 * 4)

// bucket from descending key30 (monotone-consistent with key order):
// score = bits(0x3F7FFFFF - key30); bucket 0 = highest scores. Uniform in VALUE.
__device__ __forceinline__ unsigned bucket_of(unsigned key30) {
    float s = __uint_as_float(0x3F7FFFFFu - key30);
    unsigned q = (unsigned)__fmul_rn(s, 4096.f);
    if (q > 4095u) q = 4095u;
    return 4095u - q;
}

// Exact-threshold suppression test: guard band + exact division fallback.
__device__ __forceinline__ bool suppress_test(float4 sb, float sa, float4 bx, float ab) {
    float yy1 = fmaxf(sb.x, bx.x);
    float xx1 = fmaxf(sb.y, bx.y);
    float yy2 = fminf(sb.z, bx.z);
    float xx2 = fminf(sb.w, bx.w);
    float ih  = fmaxf(__fsub_rn(yy2, yy1), 0.f);
    float iw  = fmaxf(__fsub_rn(xx2, xx1), 0.f);
    float inter = __fmul_rn(ih, iw);
    float denom = __fadd_rn(__fsub_rn(__fadd_rn(sa, ab), inter), 1e-7f);
    float e = __fmaf_rn(-0.5f, denom, inter);
    float margin = __fmul_rn(denom, 1e-4f);
    if (e < -margin) return false;
    if (e >  margin) return true;
    return __fdiv_rn(inter, denom) >= 0.5f;       // exact reference semantics
}

__global__ void __launch_bounds__(THREADS, 1)
roi_kernel(const float* __restrict__ deltas,
           const float* __restrict__ labels,
           const float* __restrict__ anchors,
           const float* __restrict__ gt,
           float* __restrict__ out)
{
    extern __shared__ unsigned s_dyn[];
    unsigned long long* s_key = (unsigned long long*)s_dyn;
    unsigned* s_hist = s_dyn;                        // alias (phase A only)
    unsigned* s_cum  = s_dyn + OFF_CUM;              // 4097 entries
    float4*   s_kbox = (float4*)(s_dyn + OFF_KBOX);  // 512 compacted boxes
    unsigned* s_mask = s_dyn + OFF_MASK;             // 512 rows x 16 words

    __shared__ float4 s_sel[TOPN];
    __shared__ float  s_sela[TOPN];
    __shared__ float4 s_nms[TOPN];
    __shared__ float  s_merged[TOPN];
    __shared__ int    s_gtbest[TOPN];
    __shared__ float4 s_gt4[NGT];
    __shared__ unsigned s_warp[32];
    __shared__ unsigned s_kalA[16], s_kalB[16];
    __shared__ int    s_ncur, s_m, s_M;

    const int b = blockIdx.x;
    const int t = threadIdx.x;
    const int lane = t & 31, wid = t >> 5;
    const int p    = t & (CHK - 1);   // candidate slot within chunk
    const int grp  = t >> 9;          // 0 or 1

    const float4* anc4 = (const float4*)(anchors) + (size_t)b * NPB;
    const float4* dlt4 = (const float4*)(deltas)  + (size_t)b * NPB;
    const float*  lab  = labels + (size_t)b * NPB;
    float4*   boxes = g_boxes + (size_t)b * NPB;
    unsigned* k30g  = g_k30  + (size_t)b * NPB;

    // ================= Phase A: decode + key30 + bucket histogram ==========
    #pragma unroll
    for (int c = 0; c < 4; ++c) s_hist[c * 1024 + t] = 0;
    if (t == 0) s_ncur = 0;
    __syncthreads();

    #pragma unroll 4
    for (int k = 0; k < PER_TH; ++k) {
        int i = t + k * THREADS;
        float4 a = anc4[i];
        float4 d = dlt4[i];
        float ah  = __fsub_rn(a.z, a.x);
        float aw  = __fsub_rn(a.w, a.y);
        float acy = __fadd_rn(a.x, __fmul_rn(0.5f, ah));
        float acx = __fadd_rn(a.y, __fmul_rn(0.5f, aw));
        float h   = __fmul_rn(expf(d.z), ah);
        float w   = __fmul_rn(expf(d.w), aw);
        float cy  = __fadd_rn(__fmul_rn(d.x, ah), acy);
        float cx  = __fadd_rn(__fmul_rn(d.y, aw), acx);
        float y1  = __fsub_rn(cy, __fmul_rn(0.5f, h));
        float x1  = __fsub_rn(cx, __fmul_rn(0.5f, w));
        boxes[i]  = make_float4(y1, x1, __fadd_rn(y1, h), __fadd_rn(x1, w));
        unsigned key30 = 0x3F7FFFFFu - __float_as_uint(lab[i]);
        k30g[i] = key30;
        atomicAdd(&s_hist[bucket_of(key30)], 1u);
    }
    __syncthreads();

    // ================= Phase B: exclusive scan of 4096 bucket counts =======
    {
        unsigned v[4], sum = 0;
        #pragma unroll
        for (int j = 0; j < 4; ++j) { v[j] = s_hist[t * 4 + j]; }
        unsigned e[4];
        #pragma unroll
        for (int j = 0; j < 4; ++j) { e[j] = sum; sum += v[j]; }
        unsigned x = sum;
        #pragma unroll
        for (int o = 1; o < 32; o <<= 1) {
            unsigned y = __shfl_up_sync(0xffffffffu, x, o);
            if (lane >= o) x += y;
        }
        if (lane == 31) s_warp[wid] = x;
        __syncthreads();
        if (t < 32) {
            unsigned wsum = s_warp[t], xx = wsum;
            #pragma unroll
            for (int o = 1; o < 32; o <<= 1) {
                unsigned y = __shfl_up_sync(0xffffffffu, xx, o);
                if (t >= o) xx += y;
            }
            s_warp[t] = xx - wsum;
        }
        __syncthreads();
        unsigned prefix = s_warp[wid] + (x - sum);
        #pragma unroll
        for (int j = 0; j < 4; ++j) s_cum[t * 4 + j] = prefix + e[j];
        if (t == THREADS - 1) s_cum[NBUCK] = prefix + sum;
        __syncthreads();
    }

    // ================= Phase C: slabs (gather -> bitonic -> chunked NMS) ===
    for (int slab = 0; slab < NSLAB; ++slab) {
        if (s_ncur >= TOPN) break;            // uniform (post-sync)
        if (t == 0) s_m = 0;
        __syncthreads();

        // gather slab members (coalesced re-scan of key30)
        #pragma unroll 4
        for (int k = 0; k < PER_TH; ++k) {
            int i = t + k * THREADS;
            unsigned key30 = k30g[i];
            unsigned bk = bucket_of(key30);
            if (s_cum[bk] / SLABSZ == (unsigned)slab) {
                int pos = atomicAdd(&s_m, 1);
                if (pos < PPOW)
                    s_key[pos] = ((unsigned long long)key30 << 16) | (unsigned)i;
            }
        }
        __syncthreads();
        int m = s_m; if (m > PPOW) m = PPOW;
        for (int i = t; i < PPOW; i += THREADS)
            if (i >= m) s_key[i] = ~0ull;
        __syncthreads();

        // bitonic sort PPOW u64 keys ascending (score desc, idx asc)
        for (int k = 2; k <= PPOW; k <<= 1) {
            for (int j = k >> 1; j > 0; j >>= 1) {
                #pragma unroll 2
                for (int n = t; n < PPOW; n += THREADS) {
                    int ixj = n ^ j;
                    if (ixj > n) {
                        bool up = ((n & k) == 0);
                        unsigned long long va = s_key[n], vb = s_key[ixj];
                        if ((va > vb) == up) { s_key[n] = vb; s_key[ixj] = va; }
                    }
                }
                __syncthreads();
            }
        }

        // NMS over sorted slab in chunks of CHK
        for (int pos = 0; pos < m; pos += CHK) {
            if (s_ncur >= TOPN) break;        // uniform (post-sync)
            int nc = s_ncur;

            // ---- load candidate (both groups hold the same box) ----
            int ci = pos + p;
            bool valid = ci < m;
            float4 bx = make_float4(0.f, 0.f, 0.f, 0.f);
            float  ab = 0.f;
            if (valid) {
                unsigned gidx = (unsigned)(s_key[ci] & 0xFFFFu);
                bx = boxes[gidx];
                ab = __fmul_rn(__fsub_rn(bx.z, bx.x), __fsub_rn(bx.w, bx.y));
            }

            // ---- split prekill: grpA tests [0,ncA), grpB tests [ncA,nc) ----
            int ncA = (nc + 1) >> 1;
            int j0 = grp ? ncA : 0;
            int j1 = grp ? nc  : ncA;
            bool kill = !valid;
            if (valid) {
                for (int j = j0; j < j1 && !kill; ++j)
                    kill = suppress_test(s_sel[j], s_sela[j], bx, ab);
            }
            unsigned kb = __ballot_sync(0xffffffffu, kill);
            if (lane == 0) { if (grp == 0) s_kalA[wid] = kb; else s_kalB[wid - 16] = kb; }
            __syncthreads();

            // ---- merge kill info, compact alive (order-preserving) ----
            bool alive = false;
            if (grp == 0) {
                unsigned kw = s_kalA[p >> 5] | s_kalB[p >> 5];
                alive = valid && !((kw >> (p & 31)) & 1u);
            }
            unsigned bal = __ballot_sync(0xffffffffu, alive);
            if (lane == 0) s_warp[wid] = __popc(bal);
            __syncthreads();
            if (t < 32) {
                unsigned wsum = s_warp[t], xx = wsum;
                #pragma unroll
                for (int o = 1; o < 32; o <<= 1) {
                    unsigned y = __shfl_up_sync(0xffffffffu, xx, o);
                    if (t >= o) xx += y;
                }
                s_warp[t] = xx - wsum;
                if (t == 31) s_M = (int)xx;
            }
            __syncthreads();
            if (alive) {
                int cpos = (int)s_warp[wid] + __popc(bal & ((1u << lane) - 1u));
                s_kbox[cpos] = bx;
            }
            // zero suppression mask (512x16 words)
            #pragma unroll
            for (int w = 0; w < 8; ++w) s_mask[w * 1024 + t] = 0;
            __syncthreads();
            int M = s_M;
            if (M == 0) continue;             // uniform

            // ---- pair enumeration among compacted survivors ----
            if (M >= 2) {
                int half = M >> 1;
                if (p < M) {
                    float4 P = s_kbox[p];
                    float pa = __fmul_rn(__fsub_rn(P.z, P.x), __fsub_rn(P.w, P.y));
                    for (int d = 1 + grp; d <= half; d += 2) {
                        int o = p + d; if (o >= M) o -= M;
                        int a = p < o ? p : o;        // earlier = suppressor
                        int c = p < o ? o : p;
                        float4 C = s_kbox[o];
                        float ca = __fmul_rn(__fsub_rn(C.z, C.x), __fsub_rn(C.w, C.y));
                        // symmetric test (same result either operand order)
                        if (suppress_test(P, pa, C, ca))
                            atomicOr(&s_mask[a * 16 + (c >> 5)], 1u << (c & 31));
                    }
                }
            }
            __syncthreads();

            // ---- warp0 greedy resolution over the bitmask (no block BARs) --
            if (t < 32) {
                unsigned dead = 0;
                unsigned aliveW = 0;
                if (t < 16) {
                    int base = t * 32;
                    int rem = M - base;
                    aliveW = (rem >= 32) ? 0xffffffffu
                           : (rem > 0 ? ((1u << rem) - 1u) : 0u);
                }
                int n = nc;
                for (int w = 0; w < 16 && n < TOPN; ++w) {
                    unsigned cur = __shfl_sync(0xffffffffu, aliveW & ~dead, w);
                    while (cur && n < TOPN) {
                        int bitp = __ffs(cur) - 1;
                        int i = w * 32 + bitp;
                        cur &= cur - 1;
                        if (t == 0) {
                            float4 sb = s_kbox[i];
                            s_sel[n] = sb;
                            s_sela[n] = __fmul_rn(__fsub_rn(sb.z, sb.x),
                                                  __fsub_rn(sb.w, sb.y));
                        }
                        n++;
                        unsigned row = (t < 16) ? s_mask[i * 16 + t] : 0u;
                        dead |= row;
                        unsigned rw = __shfl_sync(0xffffffffu, row, w);
                        cur &= ~rw;
                    }
                }
                if (t == 0) s_ncur = n;
            }
            __syncthreads();
        }
        __syncthreads();
    }
    __syncthreads();
    const int nsel = s_ncur;

    // ================= Phase D: clip, select_rois, rank, emit ==============
    for (int j = t; j < TOPN; j += THREADS) {
        float4 bxo = make_float4(0.f, 0.f, 0.f, 0.f);
        if (j < nsel) {
            float4 vv = s_sel[j];
            bxo.x = fminf(fmaxf(vv.x, 0.f), 1.f);
            bxo.y = fminf(fmaxf(vv.y, 0.f), 1.f);
            bxo.z = fminf(fmaxf(vv.z, 0.f), 1.f);
            bxo.w = fminf(fmaxf(vv.w, 0.f), 1.f);
        }
        s_nms[j] = bxo;
    }
    for (int j = t; j < NGT; j += THREADS) {
        s_gt4[j] = ((const float4*)gt)[(size_t)b * NGT + j];
    }
    __syncthreads();

    if (t < TOPN) {
        float4 a = s_nms[t];
        float aa = __fmul_rn(__fsub_rn(a.z, a.x), __fsub_rn(a.w, a.y));
        float mg = -1.f; int bi = 0;
        #pragma unroll 4
        for (int g = 0; g < NGT; ++g) {
            float4 gb = s_gt4[g];
            float yy1 = fmaxf(a.x, gb.x);
            float xx1 = fmaxf(a.y, gb.y);
            float yy2 = fminf(a.z, gb.z);
            float xx2 = fminf(a.w, gb.w);
            float inter = __fmul_rn(fmaxf(__fsub_rn(yy2, yy1), 0.f),
                                    fmaxf(__fsub_rn(xx2, xx1), 0.f));
            float gba = __fmul_rn(__fsub_rn(gb.z, gb.x), __fsub_rn(gb.w, gb.y));
            float denom = __fadd_rn(__fsub_rn(__fadd_rn(aa, gba), inter), 1e-7f);
            float iou = __fdiv_rn(inter, denom);
            if (iou > mg) { mg = iou; bi = g; }
        }
        s_merged[t] = mg; s_gtbest[t] = bi;
    }
    __syncthreads();

    if (t < TOPN) {
        float mg = s_merged[t];
        int r = 0;
        for (int j = 0; j < TOPN; ++j) {
            float mj = s_merged[j];
            if (mj > mg || (mj == mg && j < t)) ++r;
        }
        if (r < TPOS) {
            float4 a = s_nms[t];
            float* roi = out + ((size_t)b * 128 + r) * 4;
            roi[0] = a.x; roi[1] = a.y; roi[2] = a.z; roi[3] = a.w;
            out[(size_t)BATCH * 128 * 4 + (size_t)b * TPOS + r] = (float)s_gtbest[t];
        }
    }
    for (int j = t; j < 64 * 4; j += THREADS) {
        out[((size_t)b * 128 + TPOS) * 4 + j] = 0.f;
    }
}

extern "C" void kernel_launch(void* const* d_in, const int* in_sizes, int n_in,
                              void* d_out, int out_size) {
    const float* deltas  = (const float*)d_in[0];
    const float* labels  = (const float*)d_in[1];
    const float* anchors = (const float*)d_in[2];
    const float* gt      = (const float*)d_in[3];
    float* out = (float*)d_out;
    cudaFuncSetAttribute(roi_kernel, cudaFuncAttributeMaxDynamicSharedMemorySize,
                         DYN_BYTES);
    roi_kernel<<<BATCH, THREADS, DYN_BYTES>>>(deltas, labels, anchors, gt, out);
}